// round 7
// baseline (speedup 1.0000x reference)
#include <cuda_runtime.h>
#include <math.h>
#include <stdint.h>

#define Bn 512
#define Tn 256
#define Cn 192
#define Hn 64

// Scratch (device globals = sanctioned alloc-free mechanism)
__device__ float g_qF[(size_t)Bn * 2 * 8 * 1024];  // frag-major q (tf32, pre-scaled)
__device__ float g_kT[(size_t)Bn * Hn * Tn];       // [b][h][t], tf32-rounded
__device__ float g_vT[(size_t)Bn * Hn * Tn];       // [b][h][t], tf32-rounded
__device__ float g_pos[Tn * 128];                  // [t][ pos_k | pos_q ]  fp32
__device__ float g_biasF[12 * 8 * 32 * 16];        // frag-major bias, fp32 exact

// ---------------------------------------------------------------------------
__device__ __forceinline__ unsigned f2tf(float f) {
    unsigned u;
    asm("cvt.rna.tf32.f32 %0, %1;" : "=r"(u) : "f"(f));
    return u;
}
__device__ __forceinline__ float f2tff(float f) { return __uint_as_float(f2tf(f)); }

__device__ __forceinline__ void mma_tf32(float c[4], const unsigned a[4],
                                         unsigned b0, unsigned b1) {
    asm volatile(
        "mma.sync.aligned.m16n8k8.row.col.f32.tf32.tf32.f32 "
        "{%0,%1,%2,%3}, {%4,%5,%6,%7}, {%8,%9}, {%0,%1,%2,%3};"
        : "+f"(c[0]), "+f"(c[1]), "+f"(c[2]), "+f"(c[3])
        : "r"(a[0]), "r"(a[1]), "r"(a[2]), "r"(a[3]), "r"(b0), "r"(b1));
}

__device__ __forceinline__ unsigned smaddr(const void* p) {
    return (unsigned)__cvta_generic_to_shared(p);
}
#define CP_ASYNC16(dst, src) \
    asm volatile("cp.async.ca.shared.global [%0], [%1], 16;" :: "r"(dst), "l"(src))
#define CP_COMMIT() asm volatile("cp.async.commit_group;")

// ---------------------------------------------------------------------------
// Kernel 1: QKV projection. grid (3, 512): blockIdx.x = sel, blockIdx.y = b.
// 8 warps x (32 rows x 64 cols). W pre-swizzled fragment-native (48KB):
// (b0,b1) for (kk,nt,lane) at float2 index (kk*8+nt)*32 + 8*tg+gq -> one
// conflict-free LDS.64 per mma pair. x staged in 8-k chunks, stride 12
// (banks 12gq+tg all distinct), double-buffered. 72.6KB smem, 3 CTAs/SM.
// Epilogue: kT/vT via smem transpose (stride 260) + coalesced copy.
// ---------------------------------------------------------------------------
#define XS2 12
__global__ __launch_bounds__(256, 3) void qkv_mma_kernel(const float* __restrict__ x,
                                                         const float* __restrict__ Wq,
                                                         const float* __restrict__ Wk,
                                                         const float* __restrict__ Wv) {
    extern __shared__ float sm[];
    float* W2 = sm;                                     // 12288 floats
    float* bufs[2] = { sm + 12288, sm + 12288 + 3072 }; // 3072 each

    const int sel = blockIdx.x;
    const int b = blockIdx.y;
    const int tid = threadIdx.x;
    const float* __restrict__ W = (sel == 0) ? Wq : ((sel == 1) ? Wk : Wv);
    const float* __restrict__ xc = x + (size_t)b * 256 * 192;

    // prologue: chunk 0 (k 0..7, 256 rows), 512 cp.async16
    for (int f = tid; f < 512; f += 256) {
        int r = f >> 1, h = f & 1;
        CP_ASYNC16(smaddr(bufs[0] + r * XS2 + h * 4), xc + r * 192 + h * 4);
    }
    CP_COMMIT();

    // stage W fragment-native (tf32): element (k,n) -> pair slot
    for (int f = tid; f < 12288; f += 256) {
        int k = f >> 6, n = f & 63;
        int kk = k >> 3, r = k & 7, nt = n >> 3, g = n & 7;
        int idx = (kk * 8 + nt) * 64 + ((r & 3) * 8 + g) * 2 + (r >> 2);
        W2[idx] = f2tff(W[k * 64 + n]);
    }

    const int w = tid >> 5, lane = tid & 31;
    const int gq = lane >> 2, tg = lane & 3;

    float acc[2][8][4];
#pragma unroll
    for (int r = 0; r < 2; r++)
#pragma unroll
        for (int n = 0; n < 8; n++)
#pragma unroll
            for (int i = 0; i < 4; i++) acc[r][n][i] = 0.0f;

    int buf = 0;
    for (int c = 0; c < 24; c++) {
        if (c < 23) {
            const float* src = xc + (c + 1) * 8;
            float* dst = bufs[buf ^ 1];
            for (int f = tid; f < 512; f += 256) {
                int r = f >> 1, h = f & 1;
                CP_ASYNC16(smaddr(dst + r * XS2 + h * 4), src + r * 192 + h * 4);
            }
            CP_COMMIT();
            asm volatile("cp.async.wait_group 1;");
        } else {
            asm volatile("cp.async.wait_group 0;");
        }
        __syncthreads();

        const float* xs = bufs[buf] + (w * 32) * XS2;
        unsigned a0[4], a1[4];
        a0[0] = f2tf(xs[gq * XS2 + tg]);
        a0[1] = f2tf(xs[(gq + 8) * XS2 + tg]);
        a0[2] = f2tf(xs[gq * XS2 + tg + 4]);
        a0[3] = f2tf(xs[(gq + 8) * XS2 + tg + 4]);
        a1[0] = f2tf(xs[(gq + 16) * XS2 + tg]);
        a1[1] = f2tf(xs[(gq + 24) * XS2 + tg]);
        a1[2] = f2tf(xs[(gq + 16) * XS2 + tg + 4]);
        a1[3] = f2tf(xs[(gq + 24) * XS2 + tg + 4]);

        const float2* wp = (const float2*)W2 + (size_t)c * 256 + 8 * tg + gq;
#pragma unroll
        for (int nt = 0; nt < 8; nt++) {
            float2 bv = wp[nt * 32];
            unsigned b0 = __float_as_uint(bv.x);
            unsigned b1 = __float_as_uint(bv.y);
            mma_tf32(acc[0][nt], a0, b0, b1);
            mma_tf32(acc[1][nt], a1, b0, b1);
        }
        __syncthreads();
        buf ^= 1;
    }

    if (sel == 0) {
        // q -> frag-major g_qF (pre-scaled, tf32); scattered STG (1/3 of CTAs)
        const float scale = rsqrtf(192.0f);
        const int qb = w >> 2;
        float* qf = g_qF + (((size_t)b * 2 + qb) * 8 + gq) * 1024;
        const int tg0 = (2 * tg) & 3, tg1 = (2 * tg + 1) & 3, hi = tg >> 1;
#pragma unroll
        for (int r = 0; r < 2; r++) {
            int u = (w & 3) * 2 + r;
            int half = u >> 2, base8 = (u & 3) * 8;
            int e0 = hi * 2 + half;
#pragma unroll
            for (int nt = 0; nt < 8; nt++) {
                qf[(base8 + tg0) * 32 + nt * 4 + e0]     = f2tff(acc[r][nt][0] * scale);
                qf[(base8 + tg1) * 32 + nt * 4 + e0]     = f2tff(acc[r][nt][1] * scale);
                qf[(base8 + 4 + tg0) * 32 + nt * 4 + e0] = f2tff(acc[r][nt][2] * scale);
                qf[(base8 + 4 + tg1) * 32 + nt * 4 + e0] = f2tff(acc[r][nt][3] * scale);
            }
        }
    } else {
        // kT/vT: stage transposed tile [64 col][260] in smem, copy coalesced
        float* ts = sm;                       // 64*260 = 16640 <= 18432 floats
        __syncthreads();                      // mainloop fully done re-using sm
#pragma unroll
        for (int r = 0; r < 2; r++) {
            int t0 = w * 32 + r * 16 + gq;
#pragma unroll
            for (int nt = 0; nt < 8; nt++) {
                int col = nt * 8 + 2 * tg;
                ts[col * 260 + t0]           = f2tff(acc[r][nt][0]);
                ts[(col + 1) * 260 + t0]     = f2tff(acc[r][nt][1]);
                ts[col * 260 + t0 + 8]       = f2tff(acc[r][nt][2]);
                ts[(col + 1) * 260 + t0 + 8] = f2tff(acc[r][nt][3]);
            }
        }
        __syncthreads();
        float* ob = ((sel == 1) ? g_kT : g_vT) + (size_t)b * 16384;
        for (int f = tid; f < 4096; f += 256) {
            int col = f >> 6, t4 = (f & 63) * 4;
            float4 v = *(const float4*)(ts + col * 260 + t4);
            *(float4*)(ob + col * 256 + t4) = v;
        }
    }
}

// ---------------------------------------------------------------------------
// Kernel 2: positional projections (tiny, fp32 exact)
// ---------------------------------------------------------------------------
__global__ __launch_bounds__(256) void pos_kernel(const float* __restrict__ pe,
                                                  const float* __restrict__ Wk,
                                                  const float* __restrict__ Wq) {
    int idx = blockIdx.x * 256 + threadIdx.x;
    int t = idx >> 7;
    int j = idx & 127;
    const float* __restrict__ W = (j < 64) ? Wk : Wq;
    int col = j & 63;
    float s = 0.0f;
#pragma unroll 4
    for (int c = 0; c < 192; c++) s = fmaf(pe[t * 192 + c], W[c * 64 + col], s);
    g_pos[idx] = s;
}

// ---------------------------------------------------------------------------
// Kernel 3: bias in fragment-major layout (fp32 exact dots of g_pos).
// ---------------------------------------------------------------------------
__global__ void bias_frag_kernel() {
    const int ti = blockIdx.x;
    const int w = threadIdx.y, lane = threadIdx.x;
    const int gq = lane >> 2, tg = lane & 3;
    const int qb = (ti >= 4) ? 1 : 0;
    const int jt = qb ? (ti - 4) : ti;
    const int rowg = qb * 128 + gq * 8 + w;
    const int row2 = rowg + 64;
    float* o = g_biasF + ((size_t)(ti * 8 + w) * 32 + lane) * 16;
    const float* __restrict__ pk0 = g_pos + rowg * 128;
    const float* __restrict__ pk1 = g_pos + row2 * 128;
#pragma unroll
    for (int nt = 0; nt < 4; nt++) {
        int c0 = jt * 32 + nt * 8 + 2 * tg;
        const float* __restrict__ pq0 = g_pos + c0 * 128 + 64;
        const float* __restrict__ pq1 = pq0 + 128;
        float d00 = 0.f, d01 = 0.f, d10 = 0.f, d11 = 0.f;
#pragma unroll 4
        for (int h = 0; h < 64; h++) {
            float a0 = pk0[h], a1 = pk1[h];
            float b0v = pq0[h], b1v = pq1[h];
            d00 = fmaf(a0, b0v, d00); d01 = fmaf(a0, b1v, d01);
            d10 = fmaf(a1, b0v, d10); d11 = fmaf(a1, b1v, d11);
        }
        *(float4*)(o + nt * 4) = make_float4(d00, d01, d10, d11);
    }
}

// ---------------------------------------------------------------------------
// Kernel 4: flash-block attention (unchanged from round 6).
// ---------------------------------------------------------------------------
#define KS 40
#define VS 36
#define PS 36
__global__ __launch_bounds__(256, 2) void attn_mma_kernel(float* __restrict__ out) {
    extern __shared__ float sm[];
    float* kbuf[2] = { sm, sm + 2560 };
    float* vbuf[2] = { sm + 5120, sm + 5120 + 2304 };
    float* p_s = sm + 5120 + 4608;

    const int qb = blockIdx.x;
    const int b  = blockIdx.y;
    const int tid = threadIdx.x, w = tid >> 5, lane = tid & 31;
    const int gq = lane >> 2, tg = lane & 3;
    const int nj = (qb + 1) * 4;

    const float* __restrict__ kg = g_kT + (size_t)b * 16384;
    const float* __restrict__ vg = g_vT + (size_t)b * 16384;

    const int rowg = qb * 128 + gq * 8 + w;
    const int row2 = rowg + 64;

    unsigned qa[8][4];
    {
        const float* __restrict__ qf =
            g_qF + (((size_t)b * 2 + qb) * 8 + w) * 1024 + (size_t)lane * 32;
#pragma unroll
        for (int kk = 0; kk < 8; kk++) {
            float4 t = *(const float4*)(qf + kk * 4);
            qa[kk][0] = __float_as_uint(t.x);
            qa[kk][1] = __float_as_uint(t.y);
            qa[kk][2] = __float_as_uint(t.z);
            qa[kk][3] = __float_as_uint(t.w);
        }
    }

    float o[8][4];
#pragma unroll
    for (int n = 0; n < 8; n++)
#pragma unroll
        for (int i = 0; i < 4; i++) o[n][i] = 0.0f;
    float m0 = -1e30f, m1 = -1e30f, l0 = 0.0f, l1 = 0.0f;

    float* pw = p_s + w * 576;
    const float* __restrict__ bfw =
        g_biasF + ((size_t)(qb * 4 * 8 + w) * 32 + lane) * 16;

    for (int f = tid; f < 512; f += 256) {
        int h = f >> 3, c4 = (f & 7) * 4;
        CP_ASYNC16(smaddr(kbuf[0] + h * KS + c4), kg + h * 256 + c4);
        CP_ASYNC16(smaddr(vbuf[0] + h * VS + c4), vg + h * 256 + c4);
    }
    CP_COMMIT();

    int buf = 0;
    for (int jt = 0; jt < nj; jt++) {
        const int j0 = jt * 32;
        asm volatile("cp.async.wait_group 0;");
        __syncthreads();

        if (jt + 1 < nj) {
            const int jn = j0 + 32;
            float* kn = kbuf[buf ^ 1];
            float* vn = vbuf[buf ^ 1];
            for (int f = tid; f < 512; f += 256) {
                int h = f >> 3, c4 = (f & 7) * 4;
                CP_ASYNC16(smaddr(kn + h * KS + c4), kg + h * 256 + jn + c4);
                CP_ASYNC16(smaddr(vn + h * VS + c4), vg + h * 256 + jn + c4);
            }
            CP_COMMIT();
        }

        const float* kb = kbuf[buf];
        const float* vb = vbuf[buf];

        float s[4][4];
#pragma unroll
        for (int n = 0; n < 4; n++)
#pragma unroll
            for (int i = 0; i < 4; i++) s[n][i] = 0.0f;
#pragma unroll
        for (int kk = 0; kk < 8; kk++) {
            const float* kb2 = kb + (kk * 8 + tg) * KS + gq;
#pragma unroll
            for (int nt = 0; nt < 4; nt++) {
                unsigned b0 = __float_as_uint(kb2[nt * 8]);
                unsigned b1 = __float_as_uint(kb2[4 * KS + nt * 8]);
                mma_tf32(s[nt], qa[kk], b0, b1);
            }
        }

        const float* __restrict__ bft = bfw + (size_t)jt * 8 * 32 * 16;
#pragma unroll
        for (int nt = 0; nt < 4; nt++) {
            int c = nt * 8 + 2 * tg;
            int col = j0 + c;
            float4 bv = *(const float4*)(bft + nt * 4);
            s[nt][0] = (col     <= rowg) ? (s[nt][0] + bv.x) : -1e30f;
            s[nt][1] = (col + 1 <= rowg) ? (s[nt][1] + bv.y) : -1e30f;
            s[nt][2] = (col     <= row2) ? (s[nt][2] + bv.z) : -1e30f;
            s[nt][3] = (col + 1 <= row2) ? (s[nt][3] + bv.w) : -1e30f;
        }

        float mx0 = -1e30f, mx1 = -1e30f;
#pragma unroll
        for (int nt = 0; nt < 4; nt++) {
            mx0 = fmaxf(mx0, fmaxf(s[nt][0], s[nt][1]));
            mx1 = fmaxf(mx1, fmaxf(s[nt][2], s[nt][3]));
        }
        mx0 = fmaxf(mx0, __shfl_xor_sync(0xffffffffu, mx0, 1));
        mx0 = fmaxf(mx0, __shfl_xor_sync(0xffffffffu, mx0, 2));
        mx1 = fmaxf(mx1, __shfl_xor_sync(0xffffffffu, mx1, 1));
        mx1 = fmaxf(mx1, __shfl_xor_sync(0xffffffffu, mx1, 2));
        float mn0 = fmaxf(m0, mx0), mn1 = fmaxf(m1, mx1);
        float al0 = __expf(m0 - mn0), al1 = __expf(m1 - mn1);
        m0 = mn0; m1 = mn1;

        float sum0 = 0.0f, sum1 = 0.0f;
        float e[4][4];
#pragma unroll
        for (int nt = 0; nt < 4; nt++) {
            e[nt][0] = __expf(s[nt][0] - mn0);
            e[nt][1] = __expf(s[nt][1] - mn0);
            e[nt][2] = __expf(s[nt][2] - mn1);
            e[nt][3] = __expf(s[nt][3] - mn1);
            sum0 += e[nt][0] + e[nt][1];
            sum1 += e[nt][2] + e[nt][3];
        }
        sum0 += __shfl_xor_sync(0xffffffffu, sum0, 1);
        sum0 += __shfl_xor_sync(0xffffffffu, sum0, 2);
        sum1 += __shfl_xor_sync(0xffffffffu, sum1, 1);
        sum1 += __shfl_xor_sync(0xffffffffu, sum1, 2);
        l0 = l0 * al0 + sum0;
        l1 = l1 * al1 + sum1;

#pragma unroll
        for (int nt = 0; nt < 8; nt++) {
            o[nt][0] *= al0; o[nt][1] *= al0;
            o[nt][2] *= al1; o[nt][3] *= al1;
        }

#pragma unroll
        for (int nt = 0; nt < 4; nt++) {
            int c = nt * 8 + 2 * tg;
            *(float2*)(pw + gq * PS + c) =
                make_float2(f2tff(e[nt][0]), f2tff(e[nt][1]));
            *(float2*)(pw + (gq + 8) * PS + c) =
                make_float2(f2tff(e[nt][2]), f2tff(e[nt][3]));
        }
        __syncwarp();

#pragma unroll
        for (int ks = 0; ks < 4; ks++) {
            unsigned pa[4];
            pa[0] = __float_as_uint(pw[gq * PS + ks * 8 + tg]);
            pa[1] = __float_as_uint(pw[(gq + 8) * PS + ks * 8 + tg]);
            pa[2] = __float_as_uint(pw[gq * PS + ks * 8 + tg + 4]);
            pa[3] = __float_as_uint(pw[(gq + 8) * PS + ks * 8 + tg + 4]);
#pragma unroll
            for (int nt = 0; nt < 8; nt++) {
                const float* vb2 = vb + (nt * 8 + gq) * VS + ks * 8 + tg;
                unsigned b0 = __float_as_uint(vb2[0]);
                unsigned b1 = __float_as_uint(vb2[4]);
                mma_tf32(o[nt], pa, b0, b1);
            }
        }
        __syncwarp();

        __syncthreads();
        buf ^= 1;
    }

    float inv0 = 1.0f / l0, inv1 = 1.0f / l1;
    float* ob = out + ((size_t)b * 256) * 64;
#pragma unroll
    for (int nt = 0; nt < 8; nt++) {
        int c = nt * 8 + 2 * tg;
        *(float2*)(ob + (size_t)rowg * 64 + c) =
            make_float2(o[nt][0] * inv0, o[nt][1] * inv0);
        *(float2*)(ob + (size_t)row2 * 64 + c) =
            make_float2(o[nt][2] * inv1, o[nt][3] * inv1);
    }
}

// ---------------------------------------------------------------------------
extern "C" void kernel_launch(void* const* d_in, const int* in_sizes, int n_in,
                              void* d_out, int out_size) {
    const float* x  = (const float*)d_in[0];
    const float* Wk = (const float*)d_in[1];
    const float* Wq = (const float*)d_in[2];
    const float* Wv = (const float*)d_in[3];
    const float* pe = (const float*)d_in[4];
    float* out = (float*)d_out;
    (void)in_sizes; (void)n_in; (void)out_size;

    static bool attr_set = false;
    if (!attr_set) {
        cudaFuncSetAttribute(qkv_mma_kernel,
                             cudaFuncAttributeMaxDynamicSharedMemorySize, 73728);
        cudaFuncSetAttribute(attn_mma_kernel,
                             cudaFuncAttributeMaxDynamicSharedMemorySize, 57344);
        attr_set = true;
    }

    qkv_mma_kernel<<<dim3(3, 512), 256, 73728>>>(x, Wq, Wk, Wv);
    pos_kernel<<<128, 256>>>(pe, Wk, Wq);
    bias_frag_kernel<<<12, dim3(32, 8)>>>();
    attn_mma_kernel<<<dim3(2, 512), 256, 57344>>>(out);
}

// round 9
// speedup vs baseline: 1.7717x; 1.7717x over previous
#include <cuda_runtime.h>
#include <cuda_fp16.h>
#include <math.h>
#include <stdint.h>

#define Bn 512
#define Tn 256
#define Cn 192
#define Hn 64

// Scratch (device globals = sanctioned alloc-free mechanism)
__device__ float g_q[(size_t)Bn * Tn * Hn];      // [b*t][h], pre-scaled, tf32-rounded
__device__ float g_kT[(size_t)Bn * Hn * Tn];     // [b][h][t], tf32-rounded
__device__ float g_vT[(size_t)Bn * Hn * Tn];     // [b][h][t], tf32-rounded
__device__ float g_pos[Tn * 128];                // [t][ pos_k | pos_q ]  fp32
__device__ float g_bias[Tn * Tn];                // fp32 exact

// ---------------------------------------------------------------------------
__device__ __forceinline__ unsigned f2tf(float f) {
    unsigned u;
    asm("cvt.rna.tf32.f32 %0, %1;" : "=r"(u) : "f"(f));
    return u;
}
__device__ __forceinline__ float f2tff(float f) { return __uint_as_float(f2tf(f)); }

__device__ __forceinline__ void mma_tf32(float c[4], const unsigned a[4],
                                         unsigned b0, unsigned b1) {
    asm volatile(
        "mma.sync.aligned.m16n8k8.row.col.f32.tf32.tf32.f32 "
        "{%0,%1,%2,%3}, {%4,%5,%6,%7}, {%8,%9}, {%0,%1,%2,%3};"
        : "+f"(c[0]), "+f"(c[1]), "+f"(c[2]), "+f"(c[3])
        : "r"(a[0]), "r"(a[1]), "r"(a[2]), "r"(a[3]), "r"(b0), "r"(b1));
}

// fp16 m16n8k16: A = 4 packed-half2 regs, B = 2, C/D fp32 x4
__device__ __forceinline__ void mma_f16(float c[4], const unsigned a[4],
                                        unsigned b0, unsigned b1) {
    asm volatile(
        "mma.sync.aligned.m16n8k16.row.col.f32.f16.f16.f32 "
        "{%0,%1,%2,%3}, {%4,%5,%6,%7}, {%8,%9}, {%0,%1,%2,%3};"
        : "+f"(c[0]), "+f"(c[1]), "+f"(c[2]), "+f"(c[3])
        : "r"(a[0]), "r"(a[1]), "r"(a[2]), "r"(a[3]), "r"(b0), "r"(b1));
}

// pack two fp32 -> half2 word, lo half = first element
__device__ __forceinline__ unsigned packh2(float lo, float hi) {
    unsigned p;
    asm("cvt.rn.f16x2.f32 %0, %1, %2;" : "=r"(p) : "f"(hi), "f"(lo));
    return p;
}

__device__ __forceinline__ unsigned smaddr(const void* p) {
    return (unsigned)__cvta_generic_to_shared(p);
}
#define CP_ASYNC16(dst, src) \
    asm volatile("cp.async.ca.shared.global [%0], [%1], 16;" :: "r"(dst), "l"(src))
#define CP_COMMIT() asm volatile("cp.async.commit_group;")

// ---------------------------------------------------------------------------
// Kernel 1: QKV projection, fp16 m16n8k16 (same significand width as tf32;
// half the mma instructions). grid (3, 512): blockIdx.x = sel, blockIdx.y = b.
// 8 warps x (32 rows x 64 cols), k=192 in 6 chunks of 32 (32 mmas/chunk).
// W packed half2 fragment layout [96 k2][72] (reads banks 8tg+8nt+gq, staging
// banks n: both conflict-free). x cp.async fp32 [256][40] double-buffered.
// 109.6KB smem -> 2 CTAs/SM. Outputs fp32 (tf32-rounded), q pre-scaled.
// ---------------------------------------------------------------------------
#define WST 72
#define XST 40
__global__ __launch_bounds__(256, 2) void qkv_f16_kernel(const float* __restrict__ x,
                                                         const float* __restrict__ Wq,
                                                         const float* __restrict__ Wk,
                                                         const float* __restrict__ Wv) {
    extern __shared__ float sm[];
    unsigned* W_sh = (unsigned*)sm;                        // 96*72 = 6912 words
    float* bufs[2] = { sm + 6912, sm + 6912 + 10240 };     // 256*40 each

    const int sel = blockIdx.x;
    const int b = blockIdx.y;
    const int tid = threadIdx.x;
    const float* __restrict__ W = (sel == 0) ? Wq : ((sel == 1) ? Wk : Wv);
    const float* __restrict__ xc = x + (size_t)b * 256 * 192;

    // prologue: chunk 0 (k 0..31)
    for (int f = tid; f < 2048; f += 256) {
        int r = f >> 3, c4 = f & 7;
        CP_ASYNC16(smaddr(bufs[0] + r * XST + c4 * 4), xc + r * 192 + c4 * 4);
    }
    CP_COMMIT();

    // stage W packed half2: word (k2, n) = (W[2k2][n], W[2k2+1][n])
    for (int idx = tid; idx < 6144; idx += 256) {
        int k2 = idx >> 6, n = idx & 63;
        float lo = W[(2 * k2) * 64 + n];
        float hi = W[(2 * k2 + 1) * 64 + n];
        W_sh[k2 * WST + n] = packh2(lo, hi);
    }

    const int w = tid >> 5, lane = tid & 31;
    const int gq = lane >> 2, tg = lane & 3;

    float acc[2][8][4];
#pragma unroll
    for (int r = 0; r < 2; r++)
#pragma unroll
        for (int n = 0; n < 8; n++)
#pragma unroll
            for (int i = 0; i < 4; i++) acc[r][n][i] = 0.0f;

    int buf = 0;
    for (int c = 0; c < 6; c++) {
        if (c < 5) {
            const float* src = xc + (c + 1) * 32;
            float* dst = bufs[buf ^ 1];
            for (int f = tid; f < 2048; f += 256) {
                int r = f >> 3, c4 = f & 7;
                CP_ASYNC16(smaddr(dst + r * XST + c4 * 4), src + r * 192 + c4 * 4);
            }
            CP_COMMIT();
            asm volatile("cp.async.wait_group 1;");
        } else {
            asm volatile("cp.async.wait_group 0;");
        }
        __syncthreads();

        const float* xs = bufs[buf] + (w * 32) * XST;
#pragma unroll
        for (int ks2 = 0; ks2 < 2; ks2++) {
            const int kb = ks2 * 16 + 2 * tg;
            unsigned a0[4], a1[4];
            {
                float2 v;
                v = *(const float2*)(xs + gq * XST + kb);          a0[0] = packh2(v.x, v.y);
                v = *(const float2*)(xs + (gq + 8) * XST + kb);    a0[1] = packh2(v.x, v.y);
                v = *(const float2*)(xs + gq * XST + kb + 8);      a0[2] = packh2(v.x, v.y);
                v = *(const float2*)(xs + (gq + 8) * XST + kb + 8);a0[3] = packh2(v.x, v.y);
                v = *(const float2*)(xs + (gq + 16) * XST + kb);       a1[0] = packh2(v.x, v.y);
                v = *(const float2*)(xs + (gq + 24) * XST + kb);       a1[1] = packh2(v.x, v.y);
                v = *(const float2*)(xs + (gq + 16) * XST + kb + 8);   a1[2] = packh2(v.x, v.y);
                v = *(const float2*)(xs + (gq + 24) * XST + kb + 8);   a1[3] = packh2(v.x, v.y);
            }
            const unsigned* wb = W_sh + (c * 16 + ks2 * 8 + tg) * WST + gq;
#pragma unroll
            for (int nt = 0; nt < 8; nt++) {
                unsigned b0 = wb[nt * 8];
                unsigned b1 = wb[4 * WST + nt * 8];
                mma_f16(acc[0][nt], a0, b0, b1);
                mma_f16(acc[1][nt], a1, b0, b1);
            }
        }
        __syncthreads();
        buf ^= 1;
    }

    if (sel == 0) {
        const float scale = rsqrtf(192.0f);
        float* qo = g_q + ((size_t)b * 256 + w * 32) * 64;
#pragma unroll
        for (int r = 0; r < 2; r++) {
            int r0 = r * 16 + gq;
#pragma unroll
            for (int nt = 0; nt < 8; nt++) {
                int col = nt * 8 + 2 * tg;
                *(float2*)(qo + (size_t)r0 * 64 + col) =
                    make_float2(f2tff(acc[r][nt][0] * scale), f2tff(acc[r][nt][1] * scale));
                *(float2*)(qo + (size_t)(r0 + 8) * 64 + col) =
                    make_float2(f2tff(acc[r][nt][2] * scale), f2tff(acc[r][nt][3] * scale));
            }
        }
    } else {
        float* ob = ((sel == 1) ? g_kT : g_vT) + (size_t)b * 16384;
#pragma unroll
        for (int r = 0; r < 2; r++) {
            int t0 = w * 32 + r * 16 + gq;
#pragma unroll
            for (int nt = 0; nt < 8; nt++) {
                int col = nt * 8 + 2 * tg;
                ob[col * 256 + t0]           = f2tff(acc[r][nt][0]);
                ob[(col + 1) * 256 + t0]     = f2tff(acc[r][nt][1]);
                ob[col * 256 + t0 + 8]       = f2tff(acc[r][nt][2]);
                ob[(col + 1) * 256 + t0 + 8] = f2tff(acc[r][nt][3]);
            }
        }
    }
}

// ---------------------------------------------------------------------------
// Kernel 2 + 3: positional projections and bias (tiny, fp32 exact)
// ---------------------------------------------------------------------------
__global__ __launch_bounds__(256) void pos_kernel(const float* __restrict__ pe,
                                                  const float* __restrict__ Wk,
                                                  const float* __restrict__ Wq) {
    int idx = blockIdx.x * 256 + threadIdx.x;
    int t = idx >> 7;
    int j = idx & 127;
    const float* __restrict__ W = (j < 64) ? Wk : Wq;
    int col = j & 63;
    float s = 0.0f;
#pragma unroll 4
    for (int c = 0; c < 192; c++) s = fmaf(pe[t * 192 + c], W[c * 64 + col], s);
    g_pos[idx] = s;
}

__global__ __launch_bounds__(256) void bias_kernel() {
    int i = blockIdx.x;
    int j = threadIdx.x;
    float s = 0.0f;
#pragma unroll 4
    for (int h = 0; h < 64; h++)
        s = fmaf(g_pos[i * 128 + h], g_pos[j * 128 + 64 + h], s);
    g_bias[i * 256 + j] = s;
}

// ---------------------------------------------------------------------------
// Kernel 4: flash-block attention (round-5 version, 98.2us measured).
// ---------------------------------------------------------------------------
#define KS 40
#define VS 36
#define PS 36
__global__ __launch_bounds__(256, 2) void attn_mma_kernel(float* __restrict__ out) {
    extern __shared__ float sm[];
    float* kbuf[2] = { sm, sm + 2560 };
    float* vbuf[2] = { sm + 5120, sm + 5120 + 2304 };
    float* p_s = sm + 5120 + 4608;

    const int qb = blockIdx.x;
    const int b  = blockIdx.y;
    const int tid = threadIdx.x, w = tid >> 5, lane = tid & 31;
    const int gq = lane >> 2, tg = lane & 3;
    const int nj = (qb + 1) * 4;

    const float* __restrict__ kg = g_kT + (size_t)b * 16384;
    const float* __restrict__ vg = g_vT + (size_t)b * 16384;

    const int rowg = qb * 128 + gq * 8 + w;
    const int row2 = rowg + 64;
    unsigned qa[8][4];
    {
        const float* __restrict__ qg = g_q + ((size_t)b * 256 + qb * 128) * 64;
        const int r0 = gq * 8 + w, r1 = r0 + 64;
#pragma unroll
        for (int kk = 0; kk < 8; kk++) {
            int c = kk * 8 + tg;
            qa[kk][0] = __float_as_uint(qg[r0 * 64 + c]);
            qa[kk][1] = __float_as_uint(qg[r1 * 64 + c]);
            qa[kk][2] = __float_as_uint(qg[r0 * 64 + c + 4]);
            qa[kk][3] = __float_as_uint(qg[r1 * 64 + c + 4]);
        }
    }

    float o[8][4];
#pragma unroll
    for (int n = 0; n < 8; n++)
#pragma unroll
        for (int i = 0; i < 4; i++) o[n][i] = 0.0f;
    float m0 = -1e30f, m1 = -1e30f, l0 = 0.0f, l1 = 0.0f;

    float* pw = p_s + w * 576;

    for (int f = tid; f < 512; f += 256) {
        int h = f >> 3, c4 = (f & 7) * 4;
        CP_ASYNC16(smaddr(kbuf[0] + h * KS + c4), kg + h * 256 + c4);
        CP_ASYNC16(smaddr(vbuf[0] + h * VS + c4), vg + h * 256 + c4);
    }
    CP_COMMIT();

    int buf = 0;
    for (int jt = 0; jt < nj; jt++) {
        const int j0 = jt * 32;
        asm volatile("cp.async.wait_group 0;");
        __syncthreads();

        if (jt + 1 < nj) {
            const int jn = j0 + 32;
            float* kn = kbuf[buf ^ 1];
            float* vn = vbuf[buf ^ 1];
            for (int f = tid; f < 512; f += 256) {
                int h = f >> 3, c4 = (f & 7) * 4;
                CP_ASYNC16(smaddr(kn + h * KS + c4), kg + h * 256 + jn + c4);
                CP_ASYNC16(smaddr(vn + h * VS + c4), vg + h * 256 + jn + c4);
            }
            CP_COMMIT();
        }

        const float* kb = kbuf[buf];
        const float* vb = vbuf[buf];

        float s[4][4];
#pragma unroll
        for (int n = 0; n < 4; n++)
#pragma unroll
            for (int i = 0; i < 4; i++) s[n][i] = 0.0f;
#pragma unroll
        for (int kk = 0; kk < 8; kk++) {
            const float* kb2 = kb + (kk * 8 + tg) * KS + gq;
#pragma unroll
            for (int nt = 0; nt < 4; nt++) {
                unsigned b0 = __float_as_uint(kb2[nt * 8]);
                unsigned b1 = __float_as_uint(kb2[4 * KS + nt * 8]);
                mma_tf32(s[nt], qa[kk], b0, b1);
            }
        }

        const float* __restrict__ br0 = g_bias + (size_t)rowg * 256 + j0;
        const float* __restrict__ br1 = g_bias + (size_t)row2 * 256 + j0;
#pragma unroll
        for (int nt = 0; nt < 4; nt++) {
            int c = nt * 8 + 2 * tg;
            int col = j0 + c;
            float2 bias0 = *(const float2*)(br0 + c);
            float2 bias1 = *(const float2*)(br1 + c);
            s[nt][0] = (col     <= rowg) ? (s[nt][0] + bias0.x) : -1e30f;
            s[nt][1] = (col + 1 <= rowg) ? (s[nt][1] + bias0.y) : -1e30f;
            s[nt][2] = (col     <= row2) ? (s[nt][2] + bias1.x) : -1e30f;
            s[nt][3] = (col + 1 <= row2) ? (s[nt][3] + bias1.y) : -1e30f;
        }

        float mx0 = -1e30f, mx1 = -1e30f;
#pragma unroll
        for (int nt = 0; nt < 4; nt++) {
            mx0 = fmaxf(mx0, fmaxf(s[nt][0], s[nt][1]));
            mx1 = fmaxf(mx1, fmaxf(s[nt][2], s[nt][3]));
        }
        mx0 = fmaxf(mx0, __shfl_xor_sync(0xffffffffu, mx0, 1));
        mx0 = fmaxf(mx0, __shfl_xor_sync(0xffffffffu, mx0, 2));
        mx1 = fmaxf(mx1, __shfl_xor_sync(0xffffffffu, mx1, 1));
        mx1 = fmaxf(mx1, __shfl_xor_sync(0xffffffffu, mx1, 2));
        float mn0 = fmaxf(m0, mx0), mn1 = fmaxf(m1, mx1);
        float al0 = __expf(m0 - mn0), al1 = __expf(m1 - mn1);
        m0 = mn0; m1 = mn1;

        float sum0 = 0.0f, sum1 = 0.0f;
        float e[4][4];
#pragma unroll
        for (int nt = 0; nt < 4; nt++) {
            e[nt][0] = __expf(s[nt][0] - mn0);
            e[nt][1] = __expf(s[nt][1] - mn0);
            e[nt][2] = __expf(s[nt][2] - mn1);
            e[nt][3] = __expf(s[nt][3] - mn1);
            sum0 += e[nt][0] + e[nt][1];
            sum1 += e[nt][2] + e[nt][3];
        }
        sum0 += __shfl_xor_sync(0xffffffffu, sum0, 1);
        sum0 += __shfl_xor_sync(0xffffffffu, sum0, 2);
        sum1 += __shfl_xor_sync(0xffffffffu, sum1, 1);
        sum1 += __shfl_xor_sync(0xffffffffu, sum1, 2);
        l0 = l0 * al0 + sum0;
        l1 = l1 * al1 + sum1;

#pragma unroll
        for (int nt = 0; nt < 8; nt++) {
            o[nt][0] *= al0; o[nt][1] *= al0;
            o[nt][2] *= al1; o[nt][3] *= al1;
        }

#pragma unroll
        for (int nt = 0; nt < 4; nt++) {
            int c = nt * 8 + 2 * tg;
            *(float2*)(pw + gq * PS + c) =
                make_float2(f2tff(e[nt][0]), f2tff(e[nt][1]));
            *(float2*)(pw + (gq + 8) * PS + c) =
                make_float2(f2tff(e[nt][2]), f2tff(e[nt][3]));
        }
        __syncwarp();

#pragma unroll
        for (int ks = 0; ks < 4; ks++) {
            unsigned pa[4];
            pa[0] = __float_as_uint(pw[gq * PS + ks * 8 + tg]);
            pa[1] = __float_as_uint(pw[(gq + 8) * PS + ks * 8 + tg]);
            pa[2] = __float_as_uint(pw[gq * PS + ks * 8 + tg + 4]);
            pa[3] = __float_as_uint(pw[(gq + 8) * PS + ks * 8 + tg + 4]);
#pragma unroll
            for (int nt = 0; nt < 8; nt++) {
                const float* vb2 = vb + (nt * 8 + gq) * VS + ks * 8 + tg;
                unsigned b0 = __float_as_uint(vb2[0]);
                unsigned b1 = __float_as_uint(vb2[4]);
                mma_tf32(o[nt], pa, b0, b1);
            }
        }
        __syncwarp();

        __syncthreads();
        buf ^= 1;
    }

    float inv0 = 1.0f / l0, inv1 = 1.0f / l1;
    float* ob = out + ((size_t)b * 256) * 64;
#pragma unroll
    for (int nt = 0; nt < 8; nt++) {
        int c = nt * 8 + 2 * tg;
        *(float2*)(ob + (size_t)rowg * 64 + c) =
            make_float2(o[nt][0] * inv0, o[nt][1] * inv0);
        *(float2*)(ob + (size_t)row2 * 64 + c) =
            make_float2(o[nt][2] * inv1, o[nt][3] * inv1);
    }
}

// ---------------------------------------------------------------------------
extern "C" void kernel_launch(void* const* d_in, const int* in_sizes, int n_in,
                              void* d_out, int out_size) {
    const float* x  = (const float*)d_in[0];
    const float* Wk = (const float*)d_in[1];
    const float* Wq = (const float*)d_in[2];
    const float* Wv = (const float*)d_in[3];
    const float* pe = (const float*)d_in[4];
    float* out = (float*)d_out;
    (void)in_sizes; (void)n_in; (void)out_size;

    static bool attr_set = false;
    if (!attr_set) {
        cudaFuncSetAttribute(qkv_f16_kernel,
                             cudaFuncAttributeMaxDynamicSharedMemorySize, 109568);
        cudaFuncSetAttribute(attn_mma_kernel,
                             cudaFuncAttributeMaxDynamicSharedMemorySize, 57344);
        attr_set = true;
    }

    qkv_f16_kernel<<<dim3(3, 512), 256, 109568>>>(x, Wq, Wk, Wv);
    pos_kernel<<<128, 256>>>(pe, Wk, Wq);
    bias_kernel<<<256, 256>>>();
    attn_mma_kernel<<<dim3(2, 512), 256, 57344>>>(out);
}

// round 10
// speedup vs baseline: 2.0724x; 1.1697x over previous
#include <cuda_runtime.h>
#include <cuda_fp16.h>
#include <math.h>
#include <stdint.h>

#define Bn 512
#define Tn 256
#define Cn 192
#define Hn 64

// Scratch (device globals = sanctioned alloc-free mechanism). Packed half2 words.
__device__ unsigned g_q[(size_t)Bn * Tn * 32];   // [b*t][32w] = [t][64h] half, pre-scaled
__device__ unsigned g_k[(size_t)Bn * Tn * 32];   // [b][t][64h] half
__device__ unsigned g_vT[(size_t)Bn * 64 * 128]; // [b][64h][256t] half
__device__ float g_pos[Tn * 128];                // [t][ pos_k | pos_q ]  fp32
__device__ float g_bias[Tn * Tn];                // fp32 exact

// ---------------------------------------------------------------------------
// fp16 m16n8k16: A = 4 packed-half2 regs, B = 2, C/D fp32 x4
__device__ __forceinline__ void mma_f16(float c[4], const unsigned a[4],
                                        unsigned b0, unsigned b1) {
    asm volatile(
        "mma.sync.aligned.m16n8k16.row.col.f32.f16.f16.f32 "
        "{%0,%1,%2,%3}, {%4,%5,%6,%7}, {%8,%9}, {%0,%1,%2,%3};"
        : "+f"(c[0]), "+f"(c[1]), "+f"(c[2]), "+f"(c[3])
        : "r"(a[0]), "r"(a[1]), "r"(a[2]), "r"(a[3]), "r"(b0), "r"(b1));
}

// pack two fp32 -> half2 word, lo half = first arg
__device__ __forceinline__ unsigned packh2(float lo, float hi) {
    unsigned p;
    asm("cvt.rn.f16x2.f32 %0, %1, %2;" : "=r"(p) : "f"(hi), "f"(lo));
    return p;
}

__device__ __forceinline__ unsigned smaddr(const void* p) {
    return (unsigned)__cvta_generic_to_shared(p);
}
#define CP_ASYNC16(dst, src) \
    asm volatile("cp.async.ca.shared.global [%0], [%1], 16;" :: "r"(dst), "l"(src))
#define CP_COMMIT() asm volatile("cp.async.commit_group;")

// ---------------------------------------------------------------------------
// Kernel 1: QKV projection, fp16 m16n8k16. grid (3, 512): x = sel, y = b.
// 8 warps x (32 rows x 64 cols), k=192 in 6 chunks of 32 (32 mmas/chunk).
// W packed half2 [96 k2][72] (reads banks 8tg+8nt+gq, conflict-free).
// x cp.async fp32 [256][40] double-buffered. 109.6KB smem -> 2 CTAs/SM.
// Outputs packed half: q [t][h] (pre-scaled), k [t][h], v -> [h][t] via shfl.
// ---------------------------------------------------------------------------
#define WST 72
#define XST 40
__global__ __launch_bounds__(256, 2) void qkv_f16_kernel(const float* __restrict__ x,
                                                         const float* __restrict__ Wq,
                                                         const float* __restrict__ Wk,
                                                         const float* __restrict__ Wv) {
    extern __shared__ float sm[];
    unsigned* W_sh = (unsigned*)sm;                        // 96*72 words
    float* bufs[2] = { sm + 6912, sm + 6912 + 10240 };     // 256*40 each

    const int sel = blockIdx.x;
    const int b = blockIdx.y;
    const int tid = threadIdx.x;
    const float* __restrict__ W = (sel == 0) ? Wq : ((sel == 1) ? Wk : Wv);
    const float* __restrict__ xc = x + (size_t)b * 256 * 192;

    // prologue: chunk 0 (k 0..31)
    for (int f = tid; f < 2048; f += 256) {
        int r = f >> 3, c4 = f & 7;
        CP_ASYNC16(smaddr(bufs[0] + r * XST + c4 * 4), xc + r * 192 + c4 * 4);
    }
    CP_COMMIT();

    // stage W packed half2: word (k2, n) = (W[2k2][n], W[2k2+1][n])
    for (int idx = tid; idx < 6144; idx += 256) {
        int k2 = idx >> 6, n = idx & 63;
        W_sh[k2 * WST + n] = packh2(W[(2 * k2) * 64 + n], W[(2 * k2 + 1) * 64 + n]);
    }

    const int w = tid >> 5, lane = tid & 31;
    const int gq = lane >> 2, tg = lane & 3;

    float acc[2][8][4];
#pragma unroll
    for (int r = 0; r < 2; r++)
#pragma unroll
        for (int n = 0; n < 8; n++)
#pragma unroll
            for (int i = 0; i < 4; i++) acc[r][n][i] = 0.0f;

    int buf = 0;
    for (int c = 0; c < 6; c++) {
        if (c < 5) {
            const float* src = xc + (c + 1) * 32;
            float* dst = bufs[buf ^ 1];
            for (int f = tid; f < 2048; f += 256) {
                int r = f >> 3, c4 = f & 7;
                CP_ASYNC16(smaddr(dst + r * XST + c4 * 4), src + r * 192 + c4 * 4);
            }
            CP_COMMIT();
            asm volatile("cp.async.wait_group 1;");
        } else {
            asm volatile("cp.async.wait_group 0;");
        }
        __syncthreads();

        const float* xs = bufs[buf] + (w * 32) * XST;
#pragma unroll
        for (int ks2 = 0; ks2 < 2; ks2++) {
            const int kb = ks2 * 16 + 2 * tg;
            unsigned a0[4], a1[4];
            {
                float2 v;
                v = *(const float2*)(xs + gq * XST + kb);           a0[0] = packh2(v.x, v.y);
                v = *(const float2*)(xs + (gq + 8) * XST + kb);     a0[1] = packh2(v.x, v.y);
                v = *(const float2*)(xs + gq * XST + kb + 8);       a0[2] = packh2(v.x, v.y);
                v = *(const float2*)(xs + (gq + 8) * XST + kb + 8); a0[3] = packh2(v.x, v.y);
                v = *(const float2*)(xs + (gq + 16) * XST + kb);        a1[0] = packh2(v.x, v.y);
                v = *(const float2*)(xs + (gq + 24) * XST + kb);        a1[1] = packh2(v.x, v.y);
                v = *(const float2*)(xs + (gq + 16) * XST + kb + 8);    a1[2] = packh2(v.x, v.y);
                v = *(const float2*)(xs + (gq + 24) * XST + kb + 8);    a1[3] = packh2(v.x, v.y);
            }
            const unsigned* wb = W_sh + (c * 16 + ks2 * 8 + tg) * WST + gq;
#pragma unroll
            for (int nt = 0; nt < 8; nt++) {
                unsigned b0 = wb[nt * 8];
                unsigned b1 = wb[4 * WST + nt * 8];
                mma_f16(acc[0][nt], a0, b0, b1);
                mma_f16(acc[1][nt], a1, b0, b1);
            }
        }
        __syncthreads();
        buf ^= 1;
    }

    if (sel == 0) {
        const float scale = rsqrtf(192.0f);
        unsigned* qo = g_q + ((size_t)b * 256 + w * 32) * 32;
#pragma unroll
        for (int r = 0; r < 2; r++) {
            int r0 = r * 16 + gq;
#pragma unroll
            for (int nt = 0; nt < 8; nt++) {
                int wi = nt * 4 + tg;
                qo[r0 * 32 + wi] = packh2(acc[r][nt][0] * scale, acc[r][nt][1] * scale);
                qo[(r0 + 8) * 32 + wi] = packh2(acc[r][nt][2] * scale, acc[r][nt][3] * scale);
            }
        }
    } else if (sel == 1) {
        unsigned* ko = g_k + ((size_t)b * 256 + w * 32) * 32;
#pragma unroll
        for (int r = 0; r < 2; r++) {
            int r0 = r * 16 + gq;
#pragma unroll
            for (int nt = 0; nt < 8; nt++) {
                int wi = nt * 4 + tg;
                ko[r0 * 32 + wi] = packh2(acc[r][nt][0], acc[r][nt][1]);
                ko[(r0 + 8) * 32 + wi] = packh2(acc[r][nt][2], acc[r][nt][3]);
            }
        }
    } else {
        // v -> [h][t] half: adjacent t live in lanes gq, gq+1 (lane^4); even-gq
        // lanes pack (mine, partner) into one half2 word.
        unsigned* vo = g_vT + (size_t)b * 8192;
        const bool even = ((gq & 1) == 0);
#pragma unroll
        for (int r = 0; r < 2; r++) {
            int t0 = w * 32 + r * 16 + gq;
#pragma unroll
            for (int nt = 0; nt < 8; nt++) {
                int c = nt * 8 + 2 * tg;
                float a0 = acc[r][nt][0], a1 = acc[r][nt][1];
                float a2 = acc[r][nt][2], a3 = acc[r][nt][3];
                float p0 = __shfl_xor_sync(0xffffffffu, a0, 4);
                float p1 = __shfl_xor_sync(0xffffffffu, a1, 4);
                float p2 = __shfl_xor_sync(0xffffffffu, a2, 4);
                float p3 = __shfl_xor_sync(0xffffffffu, a3, 4);
                if (even) {
                    vo[c * 128 + (t0 >> 1)]           = packh2(a0, p0);
                    vo[(c + 1) * 128 + (t0 >> 1)]     = packh2(a1, p1);
                    vo[c * 128 + ((t0 + 8) >> 1)]     = packh2(a2, p2);
                    vo[(c + 1) * 128 + ((t0 + 8) >> 1)] = packh2(a3, p3);
                }
            }
        }
    }
}

// ---------------------------------------------------------------------------
// Kernel 2 + 3: positional projections and bias (tiny, fp32 exact)
// ---------------------------------------------------------------------------
__global__ __launch_bounds__(256) void pos_kernel(const float* __restrict__ pe,
                                                  const float* __restrict__ Wk,
                                                  const float* __restrict__ Wq) {
    int idx = blockIdx.x * 256 + threadIdx.x;
    int t = idx >> 7;
    int j = idx & 127;
    const float* __restrict__ W = (j < 64) ? Wk : Wq;
    int col = j & 63;
    float s = 0.0f;
#pragma unroll 4
    for (int c = 0; c < 192; c++) s = fmaf(pe[t * 192 + c], W[c * 64 + col], s);
    g_pos[idx] = s;
}

__global__ __launch_bounds__(256) void bias_kernel() {
    int i = blockIdx.x;
    int j = threadIdx.x;
    float s = 0.0f;
#pragma unroll 4
    for (int h = 0; h < 64; h++)
        s = fmaf(g_pos[i * 128 + h], g_pos[j * 128 + 64 + h], s);
    g_bias[i * 256 + j] = s;
}

// ---------------------------------------------------------------------------
// Kernel 4: flash-block attention, fp16 m16n8k16 (D layout identical to the
// proven k8 version -> softmax/mask/output math unchanged). CTA = 128 q-rows,
// grid (2,512), 8 warps. K tile [32 j][36w], V tile [64 h][20w] cp.async
// double-buffered half; P per-warp [16][20w] half. 29.7KB smem, 2 CTAs/SM.
// Bank maps verified: K 4gq+tg distinct; V/P 20gq+tg mod 32 distinct.
// ---------------------------------------------------------------------------
#define KSW 36
#define VSW 20
#define PSW 20
__global__ __launch_bounds__(256, 2) void attn_f16_kernel(float* __restrict__ out) {
    extern __shared__ unsigned smw[];
    unsigned* kbuf[2] = { smw, smw + 1152 };          // 32*36 words each
    unsigned* vbuf[2] = { smw + 2304, smw + 3584 };   // 64*20 words each
    unsigned* p_s = smw + 4864;                       // 8 * 16*20 words

    const int qb = blockIdx.x;
    const int b  = blockIdx.y;
    const int tid = threadIdx.x, w = tid >> 5, lane = tid & 31;
    const int gq = lane >> 2, tg = lane & 3;
    const int nj = (qb + 1) * 4;

    const unsigned* __restrict__ kg = g_k + (size_t)b * 8192;    // [t][32w]
    const unsigned* __restrict__ vg = g_vT + (size_t)b * 8192;   // [h][128w]

    const int rowg = qb * 128 + gq * 8 + w;
    const int row2 = rowg + 64;

    // Q fragments (packed half2): 16 x 32-bit loads
    unsigned qa[4][4];
    {
        const unsigned* __restrict__ qh = g_q + ((size_t)b * 256 + qb * 128) * 32;
        const int r0 = gq * 8 + w, r1 = r0 + 64;
#pragma unroll
        for (int kk = 0; kk < 4; kk++) {
            qa[kk][0] = qh[r0 * 32 + kk * 8 + tg];
            qa[kk][1] = qh[r1 * 32 + kk * 8 + tg];
            qa[kk][2] = qh[r0 * 32 + kk * 8 + tg + 4];
            qa[kk][3] = qh[r1 * 32 + kk * 8 + tg + 4];
        }
    }

    float o[8][4];
#pragma unroll
    for (int n = 0; n < 8; n++)
#pragma unroll
        for (int i = 0; i < 4; i++) o[n][i] = 0.0f;
    float m0 = -1e30f, m1 = -1e30f, l0 = 0.0f, l1 = 0.0f;

    unsigned* pw = p_s + w * 320;

    // Prologue: stage tile 0. K: 32 rows x 8 chunks; V: 64 rows x 4 chunks.
    for (int f = tid; f < 256; f += 256) { }
    for (int f = tid; f < 512; f += 256) {
        if (f < 256) {
            int r = f >> 3, c8 = f & 7;
            CP_ASYNC16(smaddr(kbuf[0] + r * KSW + c8 * 4), kg + r * 32 + c8 * 4);
        } else {
            int g = f - 256;
            int h = g >> 2, c4 = g & 3;
            CP_ASYNC16(smaddr(vbuf[0] + h * VSW + c4 * 4), vg + h * 128 + c4 * 4);
        }
    }
    CP_COMMIT();

    int buf = 0;
    for (int jt = 0; jt < nj; jt++) {
        const int j0 = jt * 32;
        asm volatile("cp.async.wait_group 0;");
        __syncthreads();

        if (jt + 1 < nj) {
            const int jn = j0 + 32;
            unsigned* kn = kbuf[buf ^ 1];
            unsigned* vn = vbuf[buf ^ 1];
            for (int f = tid; f < 512; f += 256) {
                if (f < 256) {
                    int r = f >> 3, c8 = f & 7;
                    CP_ASYNC16(smaddr(kn + r * KSW + c8 * 4),
                               kg + (jn + r) * 32 + c8 * 4);
                } else {
                    int g = f - 256;
                    int h = g >> 2, c4 = g & 3;
                    CP_ASYNC16(smaddr(vn + h * VSW + c4 * 4),
                               vg + h * 128 + (jn >> 1) + c4 * 4);
                }
            }
            CP_COMMIT();
        }

        const unsigned* kb = kbuf[buf];
        const unsigned* vb = vbuf[buf];

        // S = Q K^T  (q pre-scaled): 16 mmas
        float s[4][4];
#pragma unroll
        for (int n = 0; n < 4; n++)
#pragma unroll
            for (int i = 0; i < 4; i++) s[n][i] = 0.0f;
#pragma unroll
        for (int kk = 0; kk < 4; kk++) {
#pragma unroll
            for (int nt = 0; nt < 4; nt++) {
                const unsigned* kb2 = kb + (nt * 8 + gq) * KSW + kk * 8 + tg;
                mma_f16(s[nt], qa[kk], kb2[0], kb2[4]);
            }
        }

        // + bias (fp32), causal mask  (D layout identical to k8 version)
        const float* __restrict__ br0 = g_bias + (size_t)rowg * 256 + j0;
        const float* __restrict__ br1 = g_bias + (size_t)row2 * 256 + j0;
#pragma unroll
        for (int nt = 0; nt < 4; nt++) {
            int c = nt * 8 + 2 * tg;
            int col = j0 + c;
            float2 bias0 = *(const float2*)(br0 + c);
            float2 bias1 = *(const float2*)(br1 + c);
            s[nt][0] = (col     <= rowg) ? (s[nt][0] + bias0.x) : -1e30f;
            s[nt][1] = (col + 1 <= rowg) ? (s[nt][1] + bias0.y) : -1e30f;
            s[nt][2] = (col     <= row2) ? (s[nt][2] + bias1.x) : -1e30f;
            s[nt][3] = (col + 1 <= row2) ? (s[nt][3] + bias1.y) : -1e30f;
        }

        // online softmax
        float mx0 = -1e30f, mx1 = -1e30f;
#pragma unroll
        for (int nt = 0; nt < 4; nt++) {
            mx0 = fmaxf(mx0, fmaxf(s[nt][0], s[nt][1]));
            mx1 = fmaxf(mx1, fmaxf(s[nt][2], s[nt][3]));
        }
        mx0 = fmaxf(mx0, __shfl_xor_sync(0xffffffffu, mx0, 1));
        mx0 = fmaxf(mx0, __shfl_xor_sync(0xffffffffu, mx0, 2));
        mx1 = fmaxf(mx1, __shfl_xor_sync(0xffffffffu, mx1, 1));
        mx1 = fmaxf(mx1, __shfl_xor_sync(0xffffffffu, mx1, 2));
        float mn0 = fmaxf(m0, mx0), mn1 = fmaxf(m1, mx1);
        float al0 = __expf(m0 - mn0), al1 = __expf(m1 - mn1);
        m0 = mn0; m1 = mn1;

        float sum0 = 0.0f, sum1 = 0.0f;
        float e[4][4];
#pragma unroll
        for (int nt = 0; nt < 4; nt++) {
            e[nt][0] = __expf(s[nt][0] - mn0);
            e[nt][1] = __expf(s[nt][1] - mn0);
            e[nt][2] = __expf(s[nt][2] - mn1);
            e[nt][3] = __expf(s[nt][3] - mn1);
            sum0 += e[nt][0] + e[nt][1];
            sum1 += e[nt][2] + e[nt][3];
        }
        sum0 += __shfl_xor_sync(0xffffffffu, sum0, 1);
        sum0 += __shfl_xor_sync(0xffffffffu, sum0, 2);
        sum1 += __shfl_xor_sync(0xffffffffu, sum1, 1);
        sum1 += __shfl_xor_sync(0xffffffffu, sum1, 2);
        l0 = l0 * al0 + sum0;
        l1 = l1 * al1 + sum1;

#pragma unroll
        for (int nt = 0; nt < 8; nt++) {
            o[nt][0] *= al0; o[nt][1] *= al0;
            o[nt][2] *= al1; o[nt][3] *= al1;
        }

        // stage P (packed half2) per-warp, stride 20 words
#pragma unroll
        for (int nt = 0; nt < 4; nt++) {
            pw[gq * PSW + nt * 4 + tg]       = packh2(e[nt][0], e[nt][1]);
            pw[(gq + 8) * PSW + nt * 4 + tg] = packh2(e[nt][2], e[nt][3]);
        }
        __syncwarp();

        // O += P V : 16 mmas
#pragma unroll
        for (int ks = 0; ks < 2; ks++) {
            unsigned pa[4];
            pa[0] = pw[gq * PSW + ks * 8 + tg];
            pa[1] = pw[(gq + 8) * PSW + ks * 8 + tg];
            pa[2] = pw[gq * PSW + ks * 8 + tg + 4];
            pa[3] = pw[(gq + 8) * PSW + ks * 8 + tg + 4];
#pragma unroll
            for (int nt = 0; nt < 8; nt++) {
                const unsigned* vb2 = vb + (nt * 8 + gq) * VSW + ks * 8 + tg;
                mma_f16(o[nt], pa, vb2[0], vb2[4]);
            }
        }
        __syncwarp();

        __syncthreads();
        buf ^= 1;
    }

    float inv0 = 1.0f / l0, inv1 = 1.0f / l1;
    float* ob = out + ((size_t)b * 256) * 64;
#pragma unroll
    for (int nt = 0; nt < 8; nt++) {
        int c = nt * 8 + 2 * tg;
        *(float2*)(ob + (size_t)rowg * 64 + c) =
            make_float2(o[nt][0] * inv0, o[nt][1] * inv0);
        *(float2*)(ob + (size_t)row2 * 64 + c) =
            make_float2(o[nt][2] * inv1, o[nt][3] * inv1);
    }
}

// ---------------------------------------------------------------------------
extern "C" void kernel_launch(void* const* d_in, const int* in_sizes, int n_in,
                              void* d_out, int out_size) {
    const float* x  = (const float*)d_in[0];
    const float* Wk = (const float*)d_in[1];
    const float* Wq = (const float*)d_in[2];
    const float* Wv = (const float*)d_in[3];
    const float* pe = (const float*)d_in[4];
    float* out = (float*)d_out;
    (void)in_sizes; (void)n_in; (void)out_size;

    static bool attr_set = false;
    if (!attr_set) {
        cudaFuncSetAttribute(qkv_f16_kernel,
                             cudaFuncAttributeMaxDynamicSharedMemorySize, 109568);
        cudaFuncSetAttribute(attn_f16_kernel,
                             cudaFuncAttributeMaxDynamicSharedMemorySize, 29696);
        attr_set = true;
    }

    qkv_f16_kernel<<<dim3(3, 512), 256, 109568>>>(x, Wq, Wk, Wv);
    pos_kernel<<<128, 256>>>(pe, Wk, Wq);
    bias_kernel<<<256, 256>>>();
    attn_f16_kernel<<<dim3(2, 512), 256, 29696>>>(out);
}